// round 3
// baseline (speedup 1.0000x reference)
#include <cuda_runtime.h>
#include <math.h>

#define BATCH    4096
#define T        80
#define EMB      100
#define H        256
#define HS       36          // padded SMEM stride (multiple of 4 -> 16B-aligned rows)
#define KC       32          // k-chunk for streamed weight tiles
#define M2       32          // batch rows per block
#define NTHREADS 256

typedef unsigned long long u64;

__device__ __forceinline__ u64 ffma2(u64 a, u64 b, u64 c) {
    u64 d;
    asm("fma.rn.f32x2 %0, %1, %2, %3;" : "=l"(d) : "l"(a), "l"(b), "l"(c));
    return d;
}
__device__ __forceinline__ u64 splat2(float x) {
    u64 d; asm("mov.b64 %0, {%1, %1};" : "=l"(d) : "f"(x)); return d;
}
__device__ __forceinline__ u64 pack2(float lo, float hi) {
    u64 d; asm("mov.b64 %0, {%1, %2};" : "=l"(d) : "f"(lo), "f"(hi)); return d;
}
__device__ __forceinline__ void unpack2(u64 p, float& lo, float& hi) {
    asm("mov.b64 {%0, %1}, %2;" : "=f"(lo), "=f"(hi) : "l"(p));
}

// acc[4 row-pairs][4 cols] += hs(k-major [nk][HS]) @ Wg([nk][H] row-major)
// KC=32 double-buffered weight stream, ONE __syncthreads per tile:
// the buffer overwritten at tile kt was last read at tile kt-2, and every
// thread passed tile kt-1's sync (after those reads) before storing.
__device__ __forceinline__ void gemm_stream(
    const float* __restrict__ Wg, int nk,
    const float* __restrict__ hs,
    float* __restrict__ wbuf,
    u64 acc[4][4], int tid, int r0, int c0)
{
    const float4* W4 = (const float4*)Wg;
    const int nt = (nk + KC - 1) / KC;
    float4 pre[8];
#pragma unroll
    for (int j = 0; j < 8; ++j) {
        int q = tid + j * NTHREADS;
        pre[j] = ((q >> 6) < nk) ? W4[q] : make_float4(0.f, 0.f, 0.f, 0.f);
    }
#pragma unroll 1
    for (int kt = 0; kt < nt; ++kt) {
        float* buf = wbuf + (kt & 1) * (KC * H);
#pragma unroll
        for (int j = 0; j < 8; ++j)
            ((float4*)buf)[tid + j * NTHREADS] = pre[j];
        if (kt + 1 < nt) {
#pragma unroll
            for (int j = 0; j < 8; ++j) {
                int q = tid + j * NTHREADS;
                int row = (kt + 1) * KC + (q >> 6);
                pre[j] = (row < nk) ? W4[(kt + 1) * (KC * H / 4) + q]
                                    : make_float4(0.f, 0.f, 0.f, 0.f);
            }
        }
        __syncthreads();
        const int rem = min(KC, nk - kt * KC);
        const float* hk = hs + kt * KC * HS;
#pragma unroll 4
        for (int kk = 0; kk < rem; ++kk) {
            float4 a0 = *(const float4*)&hk[kk * HS + r0];      // broadcast LDS.128
            float4 a1 = *(const float4*)&hk[kk * HS + r0 + 4];  // broadcast LDS.128
            u64 ap[4];
            ap[0] = pack2(a0.x, a0.y); ap[1] = pack2(a0.z, a0.w);
            ap[2] = pack2(a1.x, a1.y); ap[3] = pack2(a1.z, a1.w);
            float4 b = *(const float4*)&buf[kk * H + c0];       // conflict-free LDS.128
            u64 bb[4] = { splat2(b.x), splat2(b.y), splat2(b.z), splat2(b.w) };
#pragma unroll
            for (int p = 0; p < 4; ++p)
#pragma unroll
                for (int j = 0; j < 4; ++j)
                    acc[p][j] = ffma2(ap[p], bb[j], acc[p][j]);
        }
    }
}

// tanh an acc tile and write it k-major into a state array (row-quad float4 STS)
__device__ __forceinline__ void tanh_store(u64 acc[4][4], float* __restrict__ st,
                                           int r0, int c0)
{
    float t[8][4];
#pragma unroll
    for (int p = 0; p < 4; ++p)
#pragma unroll
        for (int j = 0; j < 4; ++j) {
            float lo, hi; unpack2(acc[p][j], lo, hi);
            t[2 * p][j] = tanhf(lo); t[2 * p + 1][j] = tanhf(hi);
        }
#pragma unroll
    for (int j = 0; j < 4; ++j)
#pragma unroll
        for (int ii = 0; ii < 2; ++ii) {
            float4 v = make_float4(t[4 * ii + 0][j], t[4 * ii + 1][j],
                                   t[4 * ii + 2][j], t[4 * ii + 3][j]);
            *(float4*)&st[(c0 + j) * HS + r0 + 4 * ii] = v;
        }
}

__global__ __launch_bounds__(NTHREADS, 1)
void rnn_fused_kernel(const int*   __restrict__ inputs, // [BATCH][T]
                      const float* __restrict__ emb,    // [VOCAB][EMB]
                      const float* __restrict__ W1,     // [EMB][H]
                      const float* __restrict__ U1,     // [H][H]
                      const float* __restrict__ b1,     // [H]
                      const float* __restrict__ W2,     // [H][H]
                      const float* __restrict__ U2,     // [H][H]
                      const float* __restrict__ b2,     // [H]
                      float*       __restrict__ out)    // [BATCH][H]
{
    extern __shared__ float sm[];
    float* xs   = sm;                    // EMB*HS = 3600 floats
    float* h1   = xs + EMB * HS;         // H*HS   = 9216
    float* h2   = h1 + H * HS;           // H*HS   = 9216
    float* wbuf = h2 + H * HS;           // 2*KC*H = 16384

    const int tid = threadIdx.x;
    const int ty = tid >> 6, tx = tid & 63;
    const int r0 = ty * 8, c0 = tx * 4;
    const int bb = blockIdx.x * M2;

    // zero both states
    for (int i = tid; i < 2 * H * HS; i += NTHREADS) h1[i] = 0.f;

    const float4 b1v = ((const float4*)b1)[tx];
    const float4 b2v = ((const float4*)b2)[tx];
    const u64 b1p[4] = { splat2(b1v.x), splat2(b1v.y), splat2(b1v.z), splat2(b1v.w) };
    const u64 b2p[4] = { splat2(b2v.x), splat2(b2v.y), splat2(b2v.z), splat2(b2v.w) };
    __syncthreads();

#pragma unroll 1
    for (int t = 0; t < T; ++t) {
        // ---- gather x_t : 32 rows x 25 float4 from emb, store k-major ----
        for (int i = tid; i < M2 * (EMB / 4); i += NTHREADS) {
            int r  = i / (EMB / 4);
            int kq = i % (EMB / 4);
            int tok = inputs[(bb + r) * T + t];
            float4 v = ((const float4*)emb)[tok * (EMB / 4) + kq];
            xs[(kq * 4 + 0) * HS + r] = v.x;
            xs[(kq * 4 + 1) * HS + r] = v.y;
            xs[(kq * 4 + 2) * HS + r] = v.z;
            xs[(kq * 4 + 3) * HS + r] = v.w;
        }
        __syncthreads();   // publish xs (+ h2 from previous step)

        // ---- layer 1: acc = b1 + x@W1 + h1_old@U1 ----
        u64 acc[4][4];
#pragma unroll
        for (int p = 0; p < 4; ++p)
#pragma unroll
            for (int j = 0; j < 4; ++j) acc[p][j] = b1p[j];
        gemm_stream(W1, EMB, xs, wbuf, acc, tid, r0, c0);
        gemm_stream(U1, H,   h1, wbuf, acc, tid, r0, c0);

        __syncthreads();   // all threads done reading old h1
        tanh_store(acc, h1, r0, c0);
        __syncthreads();   // new h1 visible

        // ---- layer 2: acc2 = b2 + h1_new@W2 + h2_old@U2 ----
        u64 acc2[4][4];
#pragma unroll
        for (int p = 0; p < 4; ++p)
#pragma unroll
            for (int j = 0; j < 4; ++j) acc2[p][j] = b2p[j];
        gemm_stream(W2, H, h1, wbuf, acc2, tid, r0, c0);
        gemm_stream(U2, H, h2, wbuf, acc2, tid, r0, c0);

        __syncthreads();   // all threads done reading old h2
        if (t == T - 1) {
            float tt[8][4];
#pragma unroll
            for (int p = 0; p < 4; ++p)
#pragma unroll
                for (int j = 0; j < 4; ++j) {
                    float lo, hi; unpack2(acc2[p][j], lo, hi);
                    tt[2 * p][j]     = 1.f / (1.f + expf(-tanhf(lo)));
                    tt[2 * p + 1][j] = 1.f / (1.f + expf(-tanhf(hi)));
                }
#pragma unroll
            for (int i = 0; i < 8; ++i) {
                float4 o = make_float4(tt[i][0], tt[i][1], tt[i][2], tt[i][3]);
                *(float4*)&out[(bb + r0 + i) * H + c0] = o;
            }
        } else {
            tanh_store(acc2, h2, r0, c0);
            // h2 publish handled by the sync after next step's gather
        }
    }
}

extern "C" void kernel_launch(void* const* d_in, const int* in_sizes, int n_in,
                              void* d_out, int out_size)
{
    const int*   inputs = (const int*)  d_in[0];
    const float* emb    = (const float*)d_in[1];
    const float* W1     = (const float*)d_in[2];
    const float* U1     = (const float*)d_in[3];
    const float* b1     = (const float*)d_in[4];
    const float* W2     = (const float*)d_in[5];
    const float* U2     = (const float*)d_in[6];
    const float* b2     = (const float*)d_in[7];
    float* out = (float*)d_out;

    const int smem_bytes =
        (EMB * HS + 2 * H * HS + 2 * KC * H) * (int)sizeof(float); // 153664 B

    cudaFuncSetAttribute(rnn_fused_kernel,
                         cudaFuncAttributeMaxDynamicSharedMemorySize, smem_bytes);

    rnn_fused_kernel<<<BATCH / M2, NTHREADS, smem_bytes>>>(
        inputs, emb, W1, U1, b1, W2, U2, b2, out);
}

// round 4
// speedup vs baseline: 1.6634x; 1.6634x over previous
#include <cuda_runtime.h>
#include <math.h>

#define BATCH    4096
#define T        80
#define EMB      100
#define H        256
#define HS       36          // padded SMEM stride (multiple of 4 -> 16B-aligned rows)
#define KC       32          // k-chunk for streamed weight tiles
#define M2       32          // batch rows per block
#define NTHREADS 256

typedef unsigned long long u64;

__device__ __forceinline__ u64 ffma2(u64 a, u64 b, u64 c) {
    u64 d;
    asm("fma.rn.f32x2 %0, %1, %2, %3;" : "=l"(d) : "l"(a), "l"(b), "l"(c));
    return d;
}
__device__ __forceinline__ u64 splat2(float x) {
    u64 d; asm("mov.b64 %0, {%1, %1};" : "=l"(d) : "f"(x)); return d;
}
__device__ __forceinline__ u64 pack2(float lo, float hi) {
    u64 d; asm("mov.b64 %0, {%1, %2};" : "=l"(d) : "f"(lo), "f"(hi)); return d;
}
__device__ __forceinline__ void unpack2(u64 p, float& lo, float& hi) {
    asm("mov.b64 {%0, %1}, %2;" : "=f"(lo), "=f"(hi) : "l"(p));
}

// acc[4 row-pairs][4 cols] += hs(k-major [nk][HS]) @ Wg([nk][H] row-major)
// KC=32 double-buffered weight stream, ONE __syncthreads per tile:
// the buffer overwritten at tile kt was last read at tile kt-2, and every
// thread passed tile kt-1's sync (after those reads) before storing.
__device__ __forceinline__ void gemm_stream(
    const float* __restrict__ Wg, int nk,
    const float* __restrict__ hs,
    float* __restrict__ wbuf,
    u64 acc[4][4], int tid, int r0, int c0)
{
    const float4* W4 = (const float4*)Wg;
    const int nt = (nk + KC - 1) / KC;
    float4 pre[8];
#pragma unroll
    for (int j = 0; j < 8; ++j) {
        int q = tid + j * NTHREADS;
        pre[j] = ((q >> 6) < nk) ? W4[q] : make_float4(0.f, 0.f, 0.f, 0.f);
    }
#pragma unroll 1
    for (int kt = 0; kt < nt; ++kt) {
        float* buf = wbuf + (kt & 1) * (KC * H);
#pragma unroll
        for (int j = 0; j < 8; ++j)
            ((float4*)buf)[tid + j * NTHREADS] = pre[j];
        if (kt + 1 < nt) {
#pragma unroll
            for (int j = 0; j < 8; ++j) {
                int q = tid + j * NTHREADS;
                int row = (kt + 1) * KC + (q >> 6);
                pre[j] = (row < nk) ? W4[(kt + 1) * (KC * H / 4) + q]
                                    : make_float4(0.f, 0.f, 0.f, 0.f);
            }
        }
        __syncthreads();
        const int rem = min(KC, nk - kt * KC);
        const float* hk = hs + kt * KC * HS;
#pragma unroll 4
        for (int kk = 0; kk < rem; ++kk) {
            float4 a0 = *(const float4*)&hk[kk * HS + r0];      // broadcast LDS.128
            float4 a1 = *(const float4*)&hk[kk * HS + r0 + 4];  // broadcast LDS.128
            u64 ap[4];
            ap[0] = pack2(a0.x, a0.y); ap[1] = pack2(a0.z, a0.w);
            ap[2] = pack2(a1.x, a1.y); ap[3] = pack2(a1.z, a1.w);
            float4 b = *(const float4*)&buf[kk * H + c0];       // conflict-free LDS.128
            u64 bb[4] = { splat2(b.x), splat2(b.y), splat2(b.z), splat2(b.w) };
#pragma unroll
            for (int p = 0; p < 4; ++p)
#pragma unroll
                for (int j = 0; j < 4; ++j)
                    acc[p][j] = ffma2(ap[p], bb[j], acc[p][j]);
        }
    }
}

// tanh an acc tile and write it k-major into a state array (row-quad float4 STS)
__device__ __forceinline__ void tanh_store(u64 acc[4][4], float* __restrict__ st,
                                           int r0, int c0)
{
    float t[8][4];
#pragma unroll
    for (int p = 0; p < 4; ++p)
#pragma unroll
        for (int j = 0; j < 4; ++j) {
            float lo, hi; unpack2(acc[p][j], lo, hi);
            t[2 * p][j] = tanhf(lo); t[2 * p + 1][j] = tanhf(hi);
        }
#pragma unroll
    for (int j = 0; j < 4; ++j)
#pragma unroll
        for (int ii = 0; ii < 2; ++ii) {
            float4 v = make_float4(t[4 * ii + 0][j], t[4 * ii + 1][j],
                                   t[4 * ii + 2][j], t[4 * ii + 3][j]);
            *(float4*)&st[(c0 + j) * HS + r0 + 4 * ii] = v;
        }
}

__global__ __launch_bounds__(NTHREADS, 1)
void rnn_fused_kernel(const int*   __restrict__ inputs, // [BATCH][T]
                      const float* __restrict__ emb,    // [VOCAB][EMB]
                      const float* __restrict__ W1,     // [EMB][H]
                      const float* __restrict__ U1,     // [H][H]
                      const float* __restrict__ b1,     // [H]
                      const float* __restrict__ W2,     // [H][H]
                      const float* __restrict__ U2,     // [H][H]
                      const float* __restrict__ b2,     // [H]
                      float*       __restrict__ out)    // [BATCH][H]
{
    extern __shared__ float sm[];
    float* xs   = sm;                    // EMB*HS = 3600 floats
    float* h1   = xs + EMB * HS;         // H*HS   = 9216
    float* h2   = h1 + H * HS;           // H*HS   = 9216
    float* wbuf = h2 + H * HS;           // 2*KC*H = 16384

    const int tid = threadIdx.x;
    const int ty = tid >> 6, tx = tid & 63;
    const int r0 = ty * 8, c0 = tx * 4;
    const int bb = blockIdx.x * M2;

    // zero both states
    for (int i = tid; i < 2 * H * HS; i += NTHREADS) h1[i] = 0.f;

    const float4 b1v = ((const float4*)b1)[tx];
    const float4 b2v = ((const float4*)b2)[tx];
    const u64 b1p[4] = { splat2(b1v.x), splat2(b1v.y), splat2(b1v.z), splat2(b1v.w) };
    const u64 b2p[4] = { splat2(b2v.x), splat2(b2v.y), splat2(b2v.z), splat2(b2v.w) };
    __syncthreads();

#pragma unroll 1
    for (int t = 0; t < T; ++t) {
        // ---- gather x_t : 32 rows x 25 float4 from emb, store k-major ----
        for (int i = tid; i < M2 * (EMB / 4); i += NTHREADS) {
            int r  = i / (EMB / 4);
            int kq = i % (EMB / 4);
            int tok = inputs[(bb + r) * T + t];
            float4 v = ((const float4*)emb)[tok * (EMB / 4) + kq];
            xs[(kq * 4 + 0) * HS + r] = v.x;
            xs[(kq * 4 + 1) * HS + r] = v.y;
            xs[(kq * 4 + 2) * HS + r] = v.z;
            xs[(kq * 4 + 3) * HS + r] = v.w;
        }
        __syncthreads();   // publish xs (+ h2 from previous step)

        // ---- layer 1: acc = b1 + x@W1 + h1_old@U1 ----
        u64 acc[4][4];
#pragma unroll
        for (int p = 0; p < 4; ++p)
#pragma unroll
            for (int j = 0; j < 4; ++j) acc[p][j] = b1p[j];
        gemm_stream(W1, EMB, xs, wbuf, acc, tid, r0, c0);
        gemm_stream(U1, H,   h1, wbuf, acc, tid, r0, c0);

        __syncthreads();   // all threads done reading old h1
        tanh_store(acc, h1, r0, c0);
        __syncthreads();   // new h1 visible

        // ---- layer 2: acc2 = b2 + h1_new@W2 + h2_old@U2 ----
        u64 acc2[4][4];
#pragma unroll
        for (int p = 0; p < 4; ++p)
#pragma unroll
            for (int j = 0; j < 4; ++j) acc2[p][j] = b2p[j];
        gemm_stream(W2, H, h1, wbuf, acc2, tid, r0, c0);
        gemm_stream(U2, H, h2, wbuf, acc2, tid, r0, c0);

        __syncthreads();   // all threads done reading old h2
        if (t == T - 1) {
            float tt[8][4];
#pragma unroll
            for (int p = 0; p < 4; ++p)
#pragma unroll
                for (int j = 0; j < 4; ++j) {
                    float lo, hi; unpack2(acc2[p][j], lo, hi);
                    tt[2 * p][j]     = 1.f / (1.f + expf(-tanhf(lo)));
                    tt[2 * p + 1][j] = 1.f / (1.f + expf(-tanhf(hi)));
                }
#pragma unroll
            for (int i = 0; i < 8; ++i) {
                float4 o = make_float4(tt[i][0], tt[i][1], tt[i][2], tt[i][3]);
                *(float4*)&out[(bb + r0 + i) * H + c0] = o;
            }
        } else {
            tanh_store(acc2, h2, r0, c0);
            // h2 publish handled by the sync after next step's gather
        }
    }
}

extern "C" void kernel_launch(void* const* d_in, const int* in_sizes, int n_in,
                              void* d_out, int out_size)
{
    const int*   inputs = (const int*)  d_in[0];
    const float* emb    = (const float*)d_in[1];
    const float* W1     = (const float*)d_in[2];
    const float* U1     = (const float*)d_in[3];
    const float* b1     = (const float*)d_in[4];
    const float* W2     = (const float*)d_in[5];
    const float* U2     = (const float*)d_in[6];
    const float* b2     = (const float*)d_in[7];
    float* out = (float*)d_out;

    const int smem_bytes =
        (EMB * HS + 2 * H * HS + 2 * KC * H) * (int)sizeof(float); // 153664 B

    cudaFuncSetAttribute(rnn_fused_kernel,
                         cudaFuncAttributeMaxDynamicSharedMemorySize, smem_bytes);

    rnn_fused_kernel<<<BATCH / M2, NTHREADS, smem_bytes>>>(
        inputs, emb, W1, U1, b1, W2, U2, b2, out);
}